// round 4
// baseline (speedup 1.0000x reference)
#include <cuda_runtime.h>
#include <math.h>

#define B_ 64
#define S_ 1024
#define D_ 512
#define H_ 1024
#define NCTA 128
#define NTHR 512
#define HALF 256
#define KC 32
#define SA_STR 68
#define SB_STR 33
#define SG_STR 66

typedef unsigned long long u64t;

// ---- persistent device state ----------------------------------------------
__device__ float g_h0[2][H_][B_];
__device__ float g_h1[2][H_][B_];
__device__ unsigned g_bar_count;
__device__ unsigned g_bar_gen;

// ---- helpers ---------------------------------------------------------------
__device__ __forceinline__ u64t pack2(float x, float y) {
    u64t r; asm("mov.b64 %0, {%1,%2};" : "=l"(r) : "f"(x), "f"(y)); return r;
}
__device__ __forceinline__ void unpack2(u64t v, float& x, float& y) {
    asm("mov.b64 {%0,%1}, %2;" : "=f"(x), "=f"(y) : "l"(v));
}
__device__ __forceinline__ void fma2(u64t& d, u64t a, u64t b) {
    asm("fma.rn.f32x2 %0, %1, %2, %0;" : "+l"(d) : "l"(a), "l"(b));
}
__device__ __forceinline__ float sig_(float v) { return 1.0f / (1.0f + __expf(-v)); }
// named barrier for one 256-thread half (ids 1 and 2; 0 is __syncthreads)
__device__ __forceinline__ void half_sync(int m) {
    asm volatile("bar.sync %0, %1;" :: "r"(m + 1), "r"(HALF) : "memory");
}

// ---- grid barrier (128 CTAs, all resident) ---------------------------------
__device__ __forceinline__ void grid_barrier(unsigned& gen) {
    __syncthreads();
    if (threadIdx.x == 0) {
        __threadfence();
        unsigned target = gen + 1u;
        if (atomicAdd(&g_bar_count, 1u) == NCTA - 1) {
            atomicExch(&g_bar_count, 0u);
            __threadfence();
            atomicAdd(&g_bar_gen, 1u);
        } else {
            while (*(volatile unsigned*)&g_bar_gen < target) { }
        }
        __threadfence();
    }
    gen++;
    __syncthreads();
}

// ---- staging (per half: 256 threads, chunk = 32 K x 64 B / 32 K x 32 G) ----
__device__ __forceinline__ void ldA_h(float4 pa[2], const float* __restrict__ src,
                                      int kbase, int t2) {
#pragma unroll
    for (int j = 0; j < 2; j++) {
        int idx = t2 + j * HALF, kk = idx >> 4, b4 = (idx & 15) * 4;
        pa[j] = *reinterpret_cast<const float4*>(src + (kbase + kk) * B_ + b4);
    }
}
__device__ __forceinline__ void stA_h(const float4 pa[2], float* sa, int t2) {
#pragma unroll
    for (int j = 0; j < 2; j++) {
        int idx = t2 + j * HALF, kk = idx >> 4, b4 = (idx & 15) * 4;
        *reinterpret_cast<float4*>(sa + kk * SA_STR + b4) = pa[j];
    }
}
__device__ __forceinline__ void ldA_x(float4 pa[2], const float* __restrict__ xt,
                                      int kbase, int t2) {
#pragma unroll
    for (int j = 0; j < 2; j++) {
        int idx = t2 + j * HALF, b = idx >> 3, dq = (idx & 7) * 4;
        pa[j] = *reinterpret_cast<const float4*>(xt + (size_t)b * (S_ * D_) + kbase + dq);
    }
}
__device__ __forceinline__ void stA_x(const float4 pa[2], float* sa, int t2) {
#pragma unroll
    for (int j = 0; j < 2; j++) {
        int idx = t2 + j * HALF, b = idx >> 3, dq = (idx & 7) * 4;
        sa[(dq + 0) * SA_STR + b] = pa[j].x;
        sa[(dq + 1) * SA_STR + b] = pa[j].y;
        sa[(dq + 2) * SA_STR + b] = pa[j].z;
        sa[(dq + 3) * SA_STR + b] = pa[j].w;
    }
}
__device__ __forceinline__ void ldW(float4 pw[1], const float* __restrict__ W,
                                    int Kdim, int j0, int kbase, int t2) {
    int r = t2 >> 3, kq = (t2 & 7) * 4;
    int grow = (r >> 3) * H_ + j0 + (r & 7);
    pw[0] = *reinterpret_cast<const float4*>(W + (size_t)grow * Kdim + kbase + kq);
}
__device__ __forceinline__ void stW(const float4 pw[1], float* sb, int t2) {
    int r = t2 >> 3, kq = (t2 & 7) * 4;
    sb[(kq + 0) * SB_STR + r] = pw[0].x;
    sb[(kq + 1) * SB_STR + r] = pw[0].y;
    sb[(kq + 2) * SB_STR + r] = pw[0].z;
    sb[(kq + 3) * SB_STR + r] = pw[0].w;
}

// ---- FFMA2 inner product over one staged chunk ------------------------------
__device__ __forceinline__ void compute_chunk(const float* sa, const float* sb,
                                              int g, int bgrp, u64t acc[4]) {
    const float* ap = sa + bgrp * 8;
    const float* wp = sb + g;
#pragma unroll 8
    for (int kk = 0; kk < KC; kk++) {
        float w = wp[kk * SB_STR];
        u64t wpk = pack2(w, w);
        const ulonglong2* av = reinterpret_cast<const ulonglong2*>(ap + kk * SA_STR);
        ulonglong2 a01 = av[0];
        ulonglong2 a23 = av[1];
        fma2(acc[0], a01.x, wpk);
        fma2(acc[1], a01.y, wpk);
        fma2(acc[2], a23.x, wpk);
        fma2(acc[3], a23.y, wpk);
    }
}

// one GEMM segment over this half's K range [k0, k0 + nch*KC)
// XM: 1 = x-source (transpose), 0 = h-source [K][B]
template <int XM>
__device__ __forceinline__ void gemm_part(u64t acc[4], const float* __restrict__ src,
                                          const float* __restrict__ W, int Kdim,
                                          int k0, int nch, int t2, int m, int j0,
                                          int g, int bgrp, float* sa, float* sb) {
    float4 pa[2]; float4 pw[1];
    if (XM) ldA_x(pa, src, k0, t2); else ldA_h(pa, src, k0, t2);
    ldW(pw, W, Kdim, j0, k0, t2);
    for (int c = 0; c < nch; c++) {
        half_sync(m);                    // prior chunk compute done
        if (XM) stA_x(pa, sa, t2); else stA_h(pa, sa, t2);
        stW(pw, sb, t2);
        half_sync(m);
        if (c + 1 < nch) {
            int kb = k0 + (c + 1) * KC;
            if (XM) ldA_x(pa, src, kb, t2); else ldA_h(pa, src, kb, t2);
            ldW(pw, W, Kdim, j0, kb, t2);
        }
        compute_chunk(sa, sb, g, bgrp, acc);
    }
}

__device__ __forceinline__ void scatter_gates(const u64t acc[4], float* sg,
                                              int g, int bgrp) {
    float v0, v1;
#pragma unroll
    for (int i = 0; i < 4; i++) {
        unpack2(acc[i], v0, v1);
        sg[g * SG_STR + bgrp * 8 + 2 * i] = v0;
        sg[g * SG_STR + bgrp * 8 + 2 * i + 1] = v1;
    }
}

// ---- persistent kernel ------------------------------------------------------
__global__ void __launch_bounds__(NTHR, 1) lstm_persistent_kernel(
    const float* __restrict__ x,
    const float* __restrict__ Wih0, const float* __restrict__ Whh0,
    const float* __restrict__ bih0, const float* __restrict__ bhh0,
    const float* __restrict__ Wih1, const float* __restrict__ Whh1,
    const float* __restrict__ bih1, const float* __restrict__ bhh1,
    float* __restrict__ out) {
    __shared__ float sa[2][KC * SA_STR];
    __shared__ float sb[2][KC * SB_STR];
    __shared__ float sg[2][32 * SG_STR];

    const int tid = threadIdx.x;
    const int m = tid >> 8;             // half index (K-split)
    const int t2 = tid & (HALF - 1);    // thread id within half
    const int j0 = blockIdx.x * 8;      // first hidden unit owned by CTA
    const int g = t2 & 31;              // gate row within CTA tile
    const int bgrp = t2 >> 5;           // batch group of 8
    const int cb = tid >> 3;            // cell-update: batch (0..63)
    const int cu = tid & 7;             // cell-update: unit (0..7)

    const int grow = (g >> 3) * H_ + j0 + (g & 7);
    const float bias0 = (m == 0) ? (bih0[grow] + bhh0[grow]) : 0.f;
    const float bias1 = (m == 0) ? (bih1[grow] + bhh1[grow]) : 0.f;

    float c0 = 0.f, c1 = 0.f;           // cell states for (cb, j0+cu)

    float* coutp = out + (size_t)B_ * S_ * H_;
    float* h1f = out + 2ull * B_ * S_ * H_;
    float* c1f = h1f + (size_t)B_ * H_;

    unsigned gen = *(volatile unsigned*)&g_bar_gen;

    // zero own slice of initial hidden buffers (512 threads, 512 elements)
    g_h0[0][j0 + cu][cb] = 0.f;
    g_h1[0][j0 + cu][cb] = 0.f;
    grid_barrier(gen);

    for (int t = 0; t < S_; t++) {
        const int rb = t & 1, wb = (t + 1) & 1;

        // ======== layer 0: gates = x_t@Wih0^T + h0@Whh0^T + b ========
        {
            u64t acc[4];
            u64t bp = pack2(bias0, bias0);
            acc[0] = bp; acc[1] = bp; acc[2] = bp; acc[3] = bp;
            gemm_part<1>(acc, x + (size_t)t * D_, Wih0, D_, m * (D_ / 2),
                         (D_ / 2) / KC, t2, m, j0, g, bgrp, sa[m], sb[m]);
            gemm_part<0>(acc, &g_h0[rb][0][0], Whh0, H_, m * (H_ / 2),
                         (H_ / 2) / KC, t2, m, j0, g, bgrp, sa[m], sb[m]);
            scatter_gates(acc, sg[m], g, bgrp);
            __syncthreads();
            // cell update: one (batch, unit) per thread; merge half partials
            float gi = sg[0][(0 + cu) * SG_STR + cb] + sg[1][(0 + cu) * SG_STR + cb];
            float gf = sg[0][(8 + cu) * SG_STR + cb] + sg[1][(8 + cu) * SG_STR + cb];
            float gg = sg[0][(16 + cu) * SG_STR + cb] + sg[1][(16 + cu) * SG_STR + cb];
            float go = sg[0][(24 + cu) * SG_STR + cb] + sg[1][(24 + cu) * SG_STR + cb];
            float cn = sig_(gf) * c0 + sig_(gi) * tanhf(gg);
            c0 = cn;
            g_h0[wb][j0 + cu][cb] = sig_(go) * tanhf(cn);
        }

        grid_barrier(gen);   // all h0(t) published (also protects sg reuse)

        // ======== layer 1: gates = h0_new@Wih1^T + h1@Whh1^T + b ========
        {
            u64t acc[4];
            u64t bp = pack2(bias1, bias1);
            acc[0] = bp; acc[1] = bp; acc[2] = bp; acc[3] = bp;
            gemm_part<0>(acc, &g_h0[wb][0][0], Wih1, H_, m * (H_ / 2),
                         (H_ / 2) / KC, t2, m, j0, g, bgrp, sa[m], sb[m]);
            gemm_part<0>(acc, &g_h1[rb][0][0], Whh1, H_, m * (H_ / 2),
                         (H_ / 2) / KC, t2, m, j0, g, bgrp, sa[m], sb[m]);
            scatter_gates(acc, sg[m], g, bgrp);
            __syncthreads();
            float gi = sg[0][(0 + cu) * SG_STR + cb] + sg[1][(0 + cu) * SG_STR + cb];
            float gf = sg[0][(8 + cu) * SG_STR + cb] + sg[1][(8 + cu) * SG_STR + cb];
            float gg = sg[0][(16 + cu) * SG_STR + cb] + sg[1][(16 + cu) * SG_STR + cb];
            float go = sg[0][(24 + cu) * SG_STR + cb] + sg[1][(24 + cu) * SG_STR + cb];
            float cn = sig_(gf) * c1 + sig_(gi) * tanhf(gg);
            c1 = cn;
            float hn = sig_(go) * tanhf(cn);
            g_h1[wb][j0 + cu][cb] = hn;
            size_t ob = (size_t)cb * (S_ * H_) + (size_t)t * H_ + (j0 + cu);
            out[ob] = hn;
            coutp[ob] = cn;
            if (t == S_ - 1) {
                h1f[cb * H_ + j0 + cu] = hn;
                c1f[cb * H_ + j0 + cu] = cn;
            }
        }
        __syncthreads();     // sg readers done before next step's writers
    }
}

extern "C" void kernel_launch(void* const* d_in, const int* in_sizes, int n_in,
                              void* d_out, int out_size) {
    const float* x    = (const float*)d_in[0];
    const float* Wih0 = (const float*)d_in[1];
    const float* Whh0 = (const float*)d_in[2];
    const float* bih0 = (const float*)d_in[3];
    const float* bhh0 = (const float*)d_in[4];
    const float* Wih1 = (const float*)d_in[5];
    const float* Whh1 = (const float*)d_in[6];
    const float* bih1 = (const float*)d_in[7];
    const float* bhh1 = (const float*)d_in[8];
    float* out = (float*)d_out;
    lstm_persistent_kernel<<<NCTA, NTHR>>>(x, Wih0, Whh0, bih0, bhh0,
                                           Wih1, Whh1, bih1, bhh1, out);
}

// round 9
// speedup vs baseline: 1.9658x; 1.9658x over previous
#include <cuda_runtime.h>
#include <cuda_bf16.h>
#include <math.h>
#include <stdint.h>

#define B_ 64
#define S_ 1024
#define D_ 512
#define H_ 1024
#define NCTA 128
#define NTHR 256
#define NSLAB0 96
#define NSLAB1 128
#define WSLAB 224

// ---- persistent device scratch ---------------------------------------------
__device__ __align__(128) unsigned char g_ximg[(size_t)S_ * 32 * 4096];
__device__ __align__(128) unsigned char g_wimg[(size_t)NCTA * WSLAB * 2048];
__device__ __align__(128) unsigned char g_h0img[2][64 * 4096];
__device__ __align__(128) unsigned char g_h1img[2][64 * 4096];
__device__ unsigned g_bar_count, g_bar_gen;

__device__ __forceinline__ float sig_(float v) { return 1.0f / (1.0f + __expf(-v)); }

__device__ __forceinline__ void bsplit(float x, float y, uint32_t& hw, uint32_t& lw) {
    __nv_bfloat162 h2, l2;
    h2.x = __float2bfloat16_rn(x);
    h2.y = __float2bfloat16_rn(y);
    l2.x = __float2bfloat16_rn(x - __bfloat162float(h2.x));
    l2.y = __float2bfloat16_rn(y - __bfloat162float(h2.y));
    hw = *(uint32_t*)&h2;
    lw = *(uint32_t*)&l2;
}
__device__ __forceinline__ void cp16(unsigned s, const void* g) {
    asm volatile("cp.async.cg.shared.global [%0], [%1], 16;" :: "r"(s), "l"(g));
}
#define MMA(d, a, b) asm volatile( \
    "mma.sync.aligned.m16n8k16.row.col.f32.bf16.bf16.f32 " \
    "{%0,%1,%2,%3},{%4,%5,%6,%7},{%8,%9},{%0,%1,%2,%3};" \
    : "+f"((d)[0]), "+f"((d)[1]), "+f"((d)[2]), "+f"((d)[3]) \
    : "r"((a).x), "r"((a).y), "r"((a).z), "r"((a).w), "r"((b).x), "r"((b).y))

__device__ __forceinline__ void grid_barrier(unsigned& gen) {
    __syncthreads();
    if (threadIdx.x == 0) {
        __threadfence();
        unsigned target = gen + 1u;
        if (atomicAdd(&g_bar_count, 1u) == NCTA - 1) {
            atomicExch(&g_bar_count, 0u);
            __threadfence();
            atomicAdd(&g_bar_gen, 1u);
        } else {
            while (*(volatile unsigned*)&g_bar_gen < target) { }
        }
        __threadfence();
    }
    gen++;
    __syncthreads();
}

// ---- one GEMM phase: stream nch k-slabs through a 4-stage cp.async ring ----
__device__ __forceinline__ void run_phase(
    const unsigned char* __restrict__ a0, int n0,
    const unsigned char* __restrict__ a1,
    const unsigned char* __restrict__ wsl, int nch,
    unsigned char (*ss)[6144], unsigned smb,
    int tid, int lane, int mi, int ntp, float acc[2][4]) {
#define STAGE(LC) do { \
        int lc_ = (LC); \
        const unsigned char* as_ = (lc_ < n0) ? a0 + (size_t)lc_ * 4096 \
                                              : a1 + (size_t)(lc_ - n0) * 4096; \
        const unsigned char* ws_ = wsl + (size_t)lc_ * 2048; \
        unsigned sb_ = smb + (unsigned)((lc_ & 3) * 6144); \
        if (tid < 128) { \
            cp16(sb_ + tid * 16, ws_ + tid * 16); \
            cp16(sb_ + 2048 + (tid + 128) * 16, as_ + (tid + 128) * 16); \
        } else { \
            cp16(sb_ + 2048 + (tid - 128) * 16, as_ + (tid - 128) * 16); \
        } \
        asm volatile("cp.async.commit_group;" ::: "memory"); \
    } while (0)

    STAGE(0); STAGE(1); STAGE(2);
#pragma unroll 1
    for (int lc = 0; lc < nch; lc++) {
        if (lc + 3 < nch) asm volatile("cp.async.wait_group 2;" ::: "memory");
        else              asm volatile("cp.async.wait_group 0;" ::: "memory");
        __syncthreads();
        const unsigned char* st = ss[lc & 3];
        const uint4* Ap = (const uint4*)(st + mi * 512 + lane * 16);
        uint4 ah = Ap[0], al = Ap[64];            // lo tile at +1024B
#pragma unroll
        for (int nti = 0; nti < 2; nti++) {
            const uint2* Bp = (const uint2*)(st + 2048 + (ntp * 2 + nti) * 256 + lane * 8);
            uint2 bh = Bp[0], bl = Bp[256];       // lo at +2048B
            MMA(acc[nti], ah, bh);
            MMA(acc[nti], ah, bl);
            MMA(acc[nti], al, bh);
        }
        if (lc + 3 < nch) STAGE(lc + 3);
    }
#undef STAGE
}

// ---- epilogue: acc -> gates smem -> cell update -> fragment h image ---------
template <int L>
__device__ __forceinline__ void epi(float acc[2][4], float* sgate, const float* sbias,
                                    int tid, int lane, int mi, int ntp, int j0, int t,
                                    float* cst, unsigned char* himg,
                                    float* out, float* coutp, float* h1f, float* c1f) {
    int r0 = mi * 16 + (lane >> 2);
#pragma unroll
    for (int nti = 0; nti < 2; nti++) {
        int cb = (ntp * 2 + nti) * 8 + (lane & 3) * 2;
        *(float2*)&sgate[r0 * 68 + cb] = make_float2(acc[nti][0], acc[nti][1]);
        *(float2*)&sgate[(r0 + 8) * 68 + cb] = make_float2(acc[nti][2], acc[nti][3]);
    }
    __syncthreads();
    int b = tid >> 2, u2 = (tid & 3) * 2;
    float hv[2], cv[2];
#pragma unroll
    for (int q = 0; q < 2; q++) {
        int u = u2 + q;
        float gi = sgate[u * 68 + b] + sbias[u];
        float gf = sgate[(8 + u) * 68 + b] + sbias[8 + u];
        float gg = sgate[(16 + u) * 68 + b] + sbias[16 + u];
        float go = sgate[(24 + u) * 68 + b] + sbias[24 + u];
        float cn = sig_(gf) * cst[q] + sig_(gi) * tanhf(gg);
        cst[q] = cn;
        cv[q] = cn;
        hv[q] = sig_(go) * tanhf(cn);
    }
    uint32_t hw, lw;
    bsplit(hv[0], hv[1], hw, lw);
    int ph = (j0 + u2) >> 1;
    size_t base = (size_t)(ph >> 3) * 4096 + (b >> 3) * 256 +
                  ((b & 7) * 4 + (ph & 3)) * 8 + ((ph & 7) >> 2) * 4;
    *(uint32_t*)(himg + base) = hw;
    *(uint32_t*)(himg + base + 2048) = lw;
    if (L == 1) {
        size_t ob = ((size_t)b * S_ + t) * H_ + j0 + u2;
        *(float2*)(out + ob) = make_float2(hv[0], hv[1]);
        *(float2*)(coutp + ob) = make_float2(cv[0], cv[1]);
        if (t == S_ - 1) {
            *(float2*)(h1f + b * H_ + j0 + u2) = make_float2(hv[0], hv[1]);
            *(float2*)(c1f + b * H_ + j0 + u2) = make_float2(cv[0], cv[1]);
        }
    }
    __syncthreads();
}

// ---- prep: pack weights into per-CTA A-fragment images ----------------------
__global__ void prep_w_kernel(const float* __restrict__ W, int Kdim, int slab_off) {
    int Kh = Kdim / 2;
    size_t i = (size_t)blockIdx.x * 256 + threadIdx.x;
    if (i >= (size_t)NCTA * 32 * Kh) return;
    int p = (int)(i % Kh);
    int r = (int)((i / Kh) % 32);
    int cta = (int)(i / ((size_t)Kh * 32));
    int grow = (r >> 3) * H_ + cta * 8 + (r & 7);
    float2 v = *(const float2*)(W + (size_t)grow * Kdim + 2 * p);
    uint32_t hw, lw;
    bsplit(v.x, v.y, hw, lw);
    int slab = slab_off + (p >> 3);
    int reg = ((p & 7) >> 2) * 2 + ((r >> 3) & 1);
    size_t base = ((size_t)cta * WSLAB + slab) * 2048 + (r >> 4) * 512 +
                  ((r & 7) * 4 + (p & 3)) * 16 + reg * 4;
    *(uint32_t*)(g_wimg + base) = hw;
    *(uint32_t*)(g_wimg + base + 1024) = lw;
}

// ---- prep: pack x into per-timestep B-fragment images -----------------------
__global__ void prep_x_kernel(const float* __restrict__ x) {
    size_t i = (size_t)blockIdx.x * 256 + threadIdx.x;
    if (i >= (size_t)B_ * S_ * (D_ / 2)) return;
    int p = (int)(i & 255);
    int t = (int)((i >> 8) & 1023);
    int b = (int)(i >> 18);
    float2 v = *(const float2*)(x + ((size_t)b * S_ + t) * D_ + 2 * p);
    uint32_t hw, lw;
    bsplit(v.x, v.y, hw, lw);
    size_t base = ((size_t)t * 32 + (p >> 3)) * 4096 + (b >> 3) * 256 +
                  ((b & 7) * 4 + (p & 3)) * 8 + ((p & 7) >> 2) * 4;
    *(uint32_t*)(g_ximg + base) = hw;
    *(uint32_t*)(g_ximg + base + 2048) = lw;
}

// ---- persistent main kernel -------------------------------------------------
__global__ void __launch_bounds__(NTHR, 1) lstm_mma_kernel(
    const float* __restrict__ bih0, const float* __restrict__ bhh0,
    const float* __restrict__ bih1, const float* __restrict__ bhh1,
    float* __restrict__ out) {
    __shared__ __align__(128) unsigned char ssta[4][6144];
    __shared__ float sgate[32 * 68];
    __shared__ float sbias[2][32];

    const int tid = threadIdx.x, lane = tid & 31, wid = tid >> 5;
    const int mi = wid & 1, ntp = wid >> 1;
    const int cta = blockIdx.x, j0 = cta * 8;
    const unsigned smb = (unsigned)__cvta_generic_to_shared(ssta);

    if (tid < 64) {
        int L = tid >> 5, g = tid & 31;
        int grow = (g >> 3) * H_ + j0 + (g & 7);
        sbias[L][g] = L ? (bih1[grow] + bhh1[grow]) : (bih0[grow] + bhh0[grow]);
    }
    float cst0[2] = {0.f, 0.f}, cst1[2] = {0.f, 0.f};
    float* coutp = out + (size_t)B_ * S_ * H_;
    float* h1f = out + 2ull * B_ * S_ * H_;
    float* c1f = h1f + (size_t)B_ * H_;

    unsigned gen = *(volatile unsigned*)&g_bar_gen;
    {   // zero initial h images (buffer 0): 1 uint4 per thread grid-wide
        int idx = cta * NTHR + tid;
        if (idx < 16384) ((uint4*)g_h0img[0])[idx] = make_uint4(0, 0, 0, 0);
        else             ((uint4*)g_h1img[0])[idx - 16384] = make_uint4(0, 0, 0, 0);
    }
    grid_barrier(gen);

    const unsigned char* wcta = g_wimg + (size_t)cta * WSLAB * 2048;

    for (int t = 0; t < S_; t++) {
        const int rb = t & 1, wbuf = rb ^ 1;
        {
            float acc[2][4] = {{0.f, 0.f, 0.f, 0.f}, {0.f, 0.f, 0.f, 0.f}};
            run_phase(g_ximg + (size_t)t * 131072, 32, g_h0img[rb], wcta, NSLAB0,
                      ssta, smb, tid, lane, mi, ntp, acc);
            epi<0>(acc, sgate, sbias[0], tid, lane, mi, ntp, j0, t, cst0,
                   g_h0img[wbuf], out, coutp, h1f, c1f);
        }
        grid_barrier(gen);
        {
            float acc[2][4] = {{0.f, 0.f, 0.f, 0.f}, {0.f, 0.f, 0.f, 0.f}};
            run_phase(g_h0img[wbuf], 64, g_h1img[rb], wcta + (size_t)NSLAB0 * 2048,
                      NSLAB1, ssta, smb, tid, lane, mi, ntp, acc);
            epi<1>(acc, sgate, sbias[1], tid, lane, mi, ntp, j0, t, cst1,
                   g_h1img[wbuf], out, coutp, h1f, c1f);
        }
    }
}

extern "C" void kernel_launch(void* const* d_in, const int* in_sizes, int n_in,
                              void* d_out, int out_size) {
    const float* x = (const float*)d_in[0];
    prep_w_kernel<<<(NCTA * 32 * (D_ / 2) + 255) / 256, 256>>>((const float*)d_in[1], D_, 0);
    prep_w_kernel<<<(NCTA * 32 * (H_ / 2) + 255) / 256, 256>>>((const float*)d_in[2], H_, 32);
    prep_w_kernel<<<(NCTA * 32 * (H_ / 2) + 255) / 256, 256>>>((const float*)d_in[5], H_, 96);
    prep_w_kernel<<<(NCTA * 32 * (H_ / 2) + 255) / 256, 256>>>((const float*)d_in[6], H_, 160);
    prep_x_kernel<<<(int)(((size_t)B_ * S_ * (D_ / 2) + 255) / 256), 256>>>(x);
    lstm_mma_kernel<<<NCTA, NTHR>>>(
        (const float*)d_in[3], (const float*)d_in[4],
        (const float*)d_in[7], (const float*)d_in[8], (float*)d_out);
}

// round 10
// speedup vs baseline: 3.2989x; 1.6781x over previous
#include <cuda_runtime.h>
#include <cuda_bf16.h>
#include <math.h>
#include <stdint.h>

#define B_ 64
#define S_ 1024
#define D_ 512
#define H_ 1024
#define NCTA 128
#define NTHR 256
#define NSLAB0 96
#define NSLAB1 128
#define WSLAB 224
#define STB 24576            // stage bytes: 4 W slabs (8KB) + 4 A slabs (16KB)
#define DYN_SMEM (4 * STB)   // 4-slot ring = 96 KB

typedef unsigned char u8;

// ---- persistent device scratch ---------------------------------------------
__device__ __align__(128) u8 g_ximg[(size_t)S_ * 32 * 4096];
__device__ __align__(128) u8 g_wimg[(size_t)NCTA * WSLAB * 2048];
__device__ __align__(128) u8 g_h0img[2][64 * 4096];
__device__ __align__(128) u8 g_h1img[2][64 * 4096];
__device__ unsigned g_bar_count, g_bar_gen;

__device__ __forceinline__ float sig_(float v) { return 1.0f / (1.0f + __expf(-v)); }

__device__ __forceinline__ void bsplit(float x, float y, uint32_t& hw, uint32_t& lw) {
    __nv_bfloat162 h2, l2;
    h2.x = __float2bfloat16_rn(x);
    h2.y = __float2bfloat16_rn(y);
    l2.x = __float2bfloat16_rn(x - __bfloat162float(h2.x));
    l2.y = __float2bfloat16_rn(y - __bfloat162float(h2.y));
    hw = *(uint32_t*)&h2;
    lw = *(uint32_t*)&l2;
}
__device__ __forceinline__ void cp16(unsigned s, const void* g) {
    asm volatile("cp.async.cg.shared.global [%0], [%1], 16;" :: "r"(s), "l"(g));
}
#define MMA(d, a, b) asm volatile( \
    "mma.sync.aligned.m16n8k16.row.col.f32.bf16.bf16.f32 " \
    "{%0,%1,%2,%3},{%4,%5,%6,%7},{%8,%9},{%0,%1,%2,%3};" \
    : "+f"((d)[0]), "+f"((d)[1]), "+f"((d)[2]), "+f"((d)[3]) \
    : "r"((a).x), "r"((a).y), "r"((a).z), "r"((a).w), "r"((b).x), "r"((b).y))

__device__ __forceinline__ void grid_barrier(unsigned& gen) {
    __syncthreads();
    if (threadIdx.x == 0) {
        __threadfence();
        unsigned target = gen + 1u;
        if (atomicAdd(&g_bar_count, 1u) == NCTA - 1) {
            atomicExch(&g_bar_count, 0u);
            __threadfence();
            atomicAdd(&g_bar_gen, 1u);
        } else {
            while (*(volatile unsigned*)&g_bar_gen < target) { }
        }
        __threadfence();
    }
    gen++;
    __syncthreads();
}

// ---- one GEMM phase: k=64 stages through a 4-slot ring ----------------------
__device__ __forceinline__ void run_phase(
    const u8* __restrict__ a0, int n0, const u8* __restrict__ a1,
    const u8* __restrict__ wsl, int nch, u8* sstg, unsigned smb,
    int tid, int lane, int mi, int ntp, float acc[2][4]) {
    const int nstg = nch >> 2;
#define STAGE(SC) do { \
        int sc_ = (SC); int sl0_ = sc_ * 4; \
        const u8* as_ = (sl0_ < n0) ? a0 + (size_t)sl0_ * 4096 \
                                    : a1 + (size_t)(sl0_ - n0) * 4096; \
        const u8* ws_ = wsl + (size_t)sl0_ * 2048; \
        unsigned sb_ = smb + (unsigned)((sc_ & 3) * STB); \
        cp16(sb_ + tid * 16, ws_ + tid * 16); \
        cp16(sb_ + (tid + 256) * 16, ws_ + (tid + 256) * 16); \
        cp16(sb_ + 8192 + tid * 16, as_ + tid * 16); \
        cp16(sb_ + 8192 + (tid + 256) * 16, as_ + (tid + 256) * 16); \
        cp16(sb_ + 8192 + (tid + 512) * 16, as_ + (tid + 512) * 16); \
        cp16(sb_ + 8192 + (tid + 768) * 16, as_ + (tid + 768) * 16); \
        asm volatile("cp.async.commit_group;" ::: "memory"); \
    } while (0)

    STAGE(0); STAGE(1); STAGE(2);
#pragma unroll 1
    for (int sc = 0; sc < nstg; sc++) {
        if (sc + 3 < nstg) asm volatile("cp.async.wait_group 2;" ::: "memory");
        else               asm volatile("cp.async.wait_group 0;" ::: "memory");
        __syncthreads();
        const u8* st = sstg + (sc & 3) * STB;
#pragma unroll
        for (int ks = 0; ks < 4; ks++) {
            const uint4* Ap = (const uint4*)(st + ks * 2048 + mi * 512 + lane * 16);
            uint4 ah = Ap[0], al = Ap[64];      // W lo at +1024B
#pragma unroll
            for (int nti = 0; nti < 2; nti++) {
                const uint2* Bp = (const uint2*)(st + 8192 + ks * 4096 +
                                                 (ntp * 2 + nti) * 256 + lane * 8);
                uint2 bh = Bp[0], bl = Bp[256]; // act lo at +2048B
                MMA(acc[nti], ah, bh);
                MMA(acc[nti], ah, bl);
                MMA(acc[nti], al, bh);
            }
        }
        if (sc + 3 < nstg) STAGE(sc + 3);
    }
#undef STAGE
}

// ---- epilogue: acc -> gates smem -> cell update -> fragment h image ---------
template <int L>
__device__ __forceinline__ void epi(float acc[2][4], float* sgate, const float* sbias,
                                    int tid, int lane, int mi, int ntp, int j0, int t,
                                    float* cst, u8* himg,
                                    float* out, float* coutp, float* h1f, float* c1f) {
    int r0 = mi * 16 + (lane >> 2);
#pragma unroll
    for (int nti = 0; nti < 2; nti++) {
        int cb = (ntp * 2 + nti) * 8 + (lane & 3) * 2;
        *(float2*)&sgate[r0 * 68 + cb] = make_float2(acc[nti][0], acc[nti][1]);
        *(float2*)&sgate[(r0 + 8) * 68 + cb] = make_float2(acc[nti][2], acc[nti][3]);
    }
    __syncthreads();
    int b = tid >> 2, u2 = (tid & 3) * 2;
    float hv[2], cv[2];
#pragma unroll
    for (int q = 0; q < 2; q++) {
        int u = u2 + q;
        float gi = sgate[u * 68 + b] + sbias[u];
        float gf = sgate[(8 + u) * 68 + b] + sbias[8 + u];
        float gg = sgate[(16 + u) * 68 + b] + sbias[16 + u];
        float go = sgate[(24 + u) * 68 + b] + sbias[24 + u];
        float cn = sig_(gf) * cst[q] + sig_(gi) * tanhf(gg);
        cst[q] = cn;
        cv[q] = cn;
        hv[q] = sig_(go) * tanhf(cn);
    }
    uint32_t hw, lw;
    bsplit(hv[0], hv[1], hw, lw);
    int ph = (j0 + u2) >> 1;
    size_t base = (size_t)(ph >> 3) * 4096 + (b >> 3) * 256 +
                  ((b & 7) * 4 + (ph & 3)) * 8 + ((ph & 7) >> 2) * 4;
    *(uint32_t*)(himg + base) = hw;
    *(uint32_t*)(himg + base + 2048) = lw;
    if (L == 1) {
        size_t ob = ((size_t)b * S_ + t) * H_ + j0 + u2;
        *(float2*)(out + ob) = make_float2(hv[0], hv[1]);
        *(float2*)(coutp + ob) = make_float2(cv[0], cv[1]);
        if (t == S_ - 1) {
            *(float2*)(h1f + b * H_ + j0 + u2) = make_float2(hv[0], hv[1]);
            *(float2*)(c1f + b * H_ + j0 + u2) = make_float2(cv[0], cv[1]);
        }
    }
    __syncthreads();
}

// ---- persistent main kernel (prep folded into prologue) ---------------------
__global__ void __launch_bounds__(NTHR, 1) lstm_mma_kernel(
    const float* __restrict__ x,
    const float* __restrict__ Wih0, const float* __restrict__ Whh0,
    const float* __restrict__ Wih1, const float* __restrict__ Whh1,
    const float* __restrict__ bih0, const float* __restrict__ bhh0,
    const float* __restrict__ bih1, const float* __restrict__ bhh1,
    float* __restrict__ out) {
    extern __shared__ __align__(128) u8 sstg[];
    __shared__ float sgate[32 * 68];
    __shared__ float sbias[2][32];

    const int tid = threadIdx.x, lane = tid & 31, wid = tid >> 5;
    const int mi = wid & 1, ntp = wid >> 1;
    const int cta = blockIdx.x, j0 = cta * 8;
    const unsigned smb = (unsigned)__cvta_generic_to_shared(sstg);

    // ---------- prologue: pack this CTA's weight slice into fragment images --
    {
        const float* Ws[4] = { Wih0, Whh0, Wih1, Whh1 };
        const int kd[4] = { D_, H_, H_, H_ };
        const int soff[4] = { 0, 32, 96, 160 };
#pragma unroll 1
        for (int ms = 0; ms < 4; ms++) {
            int Kdim = kd[ms], Kh = Kdim >> 1;
            const float* W = Ws[ms];
#pragma unroll 1
            for (int i = tid; i < 32 * Kh; i += NTHR) {
                int p = i % Kh, r = i / Kh;
                int grow = (r >> 3) * H_ + j0 + (r & 7);
                float2 v = *(const float2*)(W + (size_t)grow * Kdim + 2 * p);
                uint32_t hw, lw;
                bsplit(v.x, v.y, hw, lw);
                int slab = soff[ms] + (p >> 3);
                size_t base = ((size_t)cta * WSLAB + slab) * 2048 + (r >> 4) * 512 +
                              ((r & 7) * 4 + (p & 3)) * 16 +
                              (((p & 7) >> 2) * 2 + ((r >> 3) & 1)) * 4;
                *(uint32_t*)(g_wimg + base) = hw;
                *(uint32_t*)(g_wimg + base + 1024) = lw;
            }
        }
        // pack x slice: global pair indices [cta*131072, +131072)
        size_t i0 = (size_t)cta * 131072;
#pragma unroll 1
        for (int k = 0; k < 512; k++) {
            size_t i = i0 + (size_t)k * NTHR + tid;
            int p = (int)(i & 255);
            int t = (int)((i >> 8) & 1023);
            int b = (int)(i >> 18);
            float2 v = *(const float2*)(x + ((size_t)b * S_ + t) * D_ + 2 * p);
            uint32_t hw, lw;
            bsplit(v.x, v.y, hw, lw);
            size_t base = ((size_t)t * 32 + (p >> 3)) * 4096 + (b >> 3) * 256 +
                          ((b & 7) * 4 + (p & 3)) * 8 + ((p & 7) >> 2) * 4;
            *(uint32_t*)(g_ximg + base) = hw;
            *(uint32_t*)(g_ximg + base + 2048) = lw;
        }
        // zero initial h images (buffer 0)
        int idx = cta * NTHR + tid;
        if (idx < 16384) ((uint4*)g_h0img[0])[idx] = make_uint4(0, 0, 0, 0);
        else             ((uint4*)g_h1img[0])[idx - 16384] = make_uint4(0, 0, 0, 0);
    }
    if (tid < 64) {
        int L = tid >> 5, g = tid & 31;
        int grow = (g >> 3) * H_ + j0 + (g & 7);
        sbias[L][g] = L ? (bih1[grow] + bhh1[grow]) : (bih0[grow] + bhh0[grow]);
    }
    float cst0[2] = {0.f, 0.f}, cst1[2] = {0.f, 0.f};
    float* coutp = out + (size_t)B_ * S_ * H_;
    float* h1f = out + 2ull * B_ * S_ * H_;
    float* c1f = h1f + (size_t)B_ * H_;

    unsigned gen = *(volatile unsigned*)&g_bar_gen;
    grid_barrier(gen);   // prep complete grid-wide

    const u8* wcta = g_wimg + (size_t)cta * WSLAB * 2048;

    for (int t = 0; t < S_; t++) {
        const int rb = t & 1, wbuf = rb ^ 1;
        {
            float acc[2][4] = {{0.f, 0.f, 0.f, 0.f}, {0.f, 0.f, 0.f, 0.f}};
            run_phase(g_ximg + (size_t)t * 131072, 32, g_h0img[rb], wcta, NSLAB0,
                      sstg, smb, tid, lane, mi, ntp, acc);
            epi<0>(acc, sgate, sbias[0], tid, lane, mi, ntp, j0, t, cst0,
                   g_h0img[wbuf], out, coutp, h1f, c1f);
        }
        grid_barrier(gen);
        {
            float acc[2][4] = {{0.f, 0.f, 0.f, 0.f}, {0.f, 0.f, 0.f, 0.f}};
            run_phase(g_h0img[wbuf], 64, g_h1img[rb], wcta + (size_t)NSLAB0 * 2048,
                      NSLAB1, sstg, smb, tid, lane, mi, ntp, acc);
            epi<1>(acc, sgate, sbias[1], tid, lane, mi, ntp, j0, t, cst1,
                   g_h1img[wbuf], out, coutp, h1f, c1f);
        }
    }
}

extern "C" void kernel_launch(void* const* d_in, const int* in_sizes, int n_in,
                              void* d_out, int out_size) {
    cudaFuncSetAttribute(lstm_mma_kernel,
                         cudaFuncAttributeMaxDynamicSharedMemorySize, DYN_SMEM);
    lstm_mma_kernel<<<NCTA, NTHR, DYN_SMEM>>>(
        (const float*)d_in[0],
        (const float*)d_in[1], (const float*)d_in[2],
        (const float*)d_in[5], (const float*)d_in[6],
        (const float*)d_in[3], (const float*)d_in[4],
        (const float*)d_in[7], (const float*)d_in[8],
        (float*)d_out);
}

// round 11
// speedup vs baseline: 3.3628x; 1.0194x over previous
#include <cuda_runtime.h>
#include <cuda_bf16.h>
#include <math.h>
#include <stdint.h>

#define B_ 64
#define S_ 1024
#define D_ 512
#define H_ 1024
#define NCTA 128
#define NTHR 256
#define NSLAB0 96
#define NSLAB1 128
#define WSLAB 224
#define STB 24576            // stage bytes: 4 W slabs (8KB) + 4 A slabs (16KB)
#define DYN_SMEM (4 * STB)   // 4-slot ring = 96 KB

typedef unsigned char u8;

// ---- persistent device scratch ---------------------------------------------
__device__ __align__(128) u8 g_ximg[(size_t)S_ * 32 * 4096];
__device__ __align__(128) u8 g_wimg[(size_t)NCTA * WSLAB * 2048];
__device__ __align__(128) u8 g_h0img[2][64 * 4096];
__device__ __align__(128) u8 g_h1img[2][64 * 4096];
__device__ unsigned g_bar_count, g_bar_gen;

__device__ __forceinline__ float sig_(float v) { return 1.0f / (1.0f + __expf(-v)); }

__device__ __forceinline__ void bsplit(float x, float y, uint32_t& hw, uint32_t& lw) {
    __nv_bfloat162 h2, l2;
    h2.x = __float2bfloat16_rn(x);
    h2.y = __float2bfloat16_rn(y);
    l2.x = __float2bfloat16_rn(x - __bfloat162float(h2.x));
    l2.y = __float2bfloat16_rn(y - __bfloat162float(h2.y));
    hw = *(uint32_t*)&h2;
    lw = *(uint32_t*)&l2;
}
__device__ __forceinline__ void cp16(unsigned s, const void* g) {
    asm volatile("cp.async.cg.shared.global [%0], [%1], 16;" :: "r"(s), "l"(g));
}
#define MMA(d, a, b) asm volatile( \
    "mma.sync.aligned.m16n8k16.row.col.f32.bf16.bf16.f32 " \
    "{%0,%1,%2,%3},{%4,%5,%6,%7},{%8,%9},{%0,%1,%2,%3};" \
    : "+f"((d)[0]), "+f"((d)[1]), "+f"((d)[2]), "+f"((d)[3]) \
    : "r"((a).x), "r"((a).y), "r"((a).z), "r"((a).w), "r"((b).x), "r"((b).y))

__device__ __forceinline__ void grid_barrier(unsigned& gen) {
    __syncthreads();
    if (threadIdx.x == 0) {
        __threadfence();
        unsigned target = gen + 1u;
        if (atomicAdd(&g_bar_count, 1u) == NCTA - 1) {
            atomicExch(&g_bar_count, 0u);
            __threadfence();
            atomicAdd(&g_bar_gen, 1u);
        } else {
            while (*(volatile unsigned*)&g_bar_gen < target) { }
        }
        __threadfence();
    }
    gen++;
    __syncthreads();
}

// ---- one GEMM phase: k=64 stages through a 4-slot ring ----------------------
// warp tile: m32 x n32, k-split 4 (warp handles ks == kspl within each stage)
__device__ __forceinline__ void run_phase(
    const u8* __restrict__ a0, int n0, const u8* __restrict__ a1,
    const u8* __restrict__ wsl, int nch, u8* sstg, unsigned smb,
    int tid, int lane, int ni2, int kspl, float acc[2][4][4]) {
    const int nstg = nch >> 2;
#define STAGE(SC) do { \
        int sc_ = (SC); int sl0_ = sc_ * 4; \
        const u8* as_ = (sl0_ < n0) ? a0 + (size_t)sl0_ * 4096 \
                                    : a1 + (size_t)(sl0_ - n0) * 4096; \
        const u8* ws_ = wsl + (size_t)sl0_ * 2048; \
        unsigned sb_ = smb + (unsigned)((sc_ & 3) * STB); \
        cp16(sb_ + tid * 16, ws_ + tid * 16); \
        cp16(sb_ + (tid + 256) * 16, ws_ + (tid + 256) * 16); \
        cp16(sb_ + 8192 + tid * 16, as_ + tid * 16); \
        cp16(sb_ + 8192 + (tid + 256) * 16, as_ + (tid + 256) * 16); \
        cp16(sb_ + 8192 + (tid + 512) * 16, as_ + (tid + 512) * 16); \
        cp16(sb_ + 8192 + (tid + 768) * 16, as_ + (tid + 768) * 16); \
        asm volatile("cp.async.commit_group;" ::: "memory"); \
    } while (0)

    STAGE(0); STAGE(1); STAGE(2);
#pragma unroll 1
    for (int sc = 0; sc < nstg; sc++) {
        if (sc + 3 < nstg) asm volatile("cp.async.wait_group 2;" ::: "memory");
        else               asm volatile("cp.async.wait_group 0;" ::: "memory");
        __syncthreads();
        const u8* st = sstg + (sc & 3) * STB;
        // A (weights): this warp's k-slab, both m16 halves, hi+lo
        const u8* ab = st + kspl * 2048 + lane * 16;
        uint4 ah0 = *(const uint4*)(ab);
        uint4 ah1 = *(const uint4*)(ab + 512);
        uint4 al0 = *(const uint4*)(ab + 1024);
        uint4 al1 = *(const uint4*)(ab + 1536);
        // B (activations): this warp's n32 half of the same k-slab, hi+lo
        const u8* bb = st + 8192 + kspl * 4096 + ni2 * 1024 + lane * 8;
        uint2 bh[4], bl[4];
#pragma unroll
        for (int n8 = 0; n8 < 4; n8++) {
            bh[n8] = *(const uint2*)(bb + n8 * 256);
            bl[n8] = *(const uint2*)(bb + 2048 + n8 * 256);
        }
#pragma unroll
        for (int n8 = 0; n8 < 4; n8++) {
            MMA(acc[0][n8], ah0, bh[n8]);
            MMA(acc[0][n8], ah0, bl[n8]);
            MMA(acc[0][n8], al0, bh[n8]);
            MMA(acc[1][n8], ah1, bh[n8]);
            MMA(acc[1][n8], ah1, bl[n8]);
            MMA(acc[1][n8], al1, bh[n8]);
        }
        if (sc + 3 < nstg) STAGE(sc + 3);
    }
#undef STAGE
}

// ---- epilogue: 4 k-split partials -> gates -> cell update -> h image --------
template <int L>
__device__ __forceinline__ void epi(float acc[2][4][4], float (*sgate)[32 * 68],
                                    const float* sbias, int tid, int lane,
                                    int ni2, int kspl, int j0, int t,
                                    float* cst, u8* himg,
                                    float* out, float* coutp, float* h1f, float* c1f) {
    int rq = lane >> 2, c0 = (lane & 3) * 2;
    float* sgk = sgate[kspl];
#pragma unroll
    for (int mi = 0; mi < 2; mi++)
#pragma unroll
        for (int n8 = 0; n8 < 4; n8++) {
            int cb = (ni2 * 4 + n8) * 8 + c0;
            int r0 = mi * 16 + rq;
            *(float2*)&sgk[r0 * 68 + cb] = make_float2(acc[mi][n8][0], acc[mi][n8][1]);
            *(float2*)&sgk[(r0 + 8) * 68 + cb] = make_float2(acc[mi][n8][2], acc[mi][n8][3]);
        }
    __syncthreads();
    int b = tid >> 2, u2 = (tid & 3) * 2;
    float hv[2], cv[2];
#pragma unroll
    for (int q = 0; q < 2; q++) {
        int u = u2 + q;
        float gi = sbias[u], gf = sbias[8 + u], gg = sbias[16 + u], go = sbias[24 + u];
#pragma unroll
        for (int c = 0; c < 4; c++) {
            gi += sgate[c][u * 68 + b];
            gf += sgate[c][(8 + u) * 68 + b];
            gg += sgate[c][(16 + u) * 68 + b];
            go += sgate[c][(24 + u) * 68 + b];
        }
        float cn = sig_(gf) * cst[q] + sig_(gi) * tanhf(gg);
        cst[q] = cn;
        cv[q] = cn;
        hv[q] = sig_(go) * tanhf(cn);
    }
    uint32_t hw, lw;
    bsplit(hv[0], hv[1], hw, lw);
    int ph = (j0 + u2) >> 1;
    size_t base = (size_t)(ph >> 3) * 4096 + (b >> 3) * 256 +
                  ((b & 7) * 4 + (ph & 3)) * 8 + ((ph & 7) >> 2) * 4;
    *(uint32_t*)(himg + base) = hw;
    *(uint32_t*)(himg + base + 2048) = lw;
    if (L == 1) {
        size_t ob = ((size_t)b * S_ + t) * H_ + j0 + u2;
        *(float2*)(out + ob) = make_float2(hv[0], hv[1]);
        *(float2*)(coutp + ob) = make_float2(cv[0], cv[1]);
        if (t == S_ - 1) {
            *(float2*)(h1f + b * H_ + j0 + u2) = make_float2(hv[0], hv[1]);
            *(float2*)(c1f + b * H_ + j0 + u2) = make_float2(cv[0], cv[1]);
        }
    }
    __syncthreads();
}

// ---- persistent main kernel (prep folded into prologue) ---------------------
__global__ void __launch_bounds__(NTHR, 1) lstm_mma_kernel(
    const float* __restrict__ x,
    const float* __restrict__ Wih0, const float* __restrict__ Whh0,
    const float* __restrict__ Wih1, const float* __restrict__ Whh1,
    const float* __restrict__ bih0, const float* __restrict__ bhh0,
    const float* __restrict__ bih1, const float* __restrict__ bhh1,
    float* __restrict__ out) {
    extern __shared__ __align__(128) u8 sstg[];
    __shared__ float sgate[4][32 * 68];
    __shared__ float sbias[2][32];

    const int tid = threadIdx.x, lane = tid & 31, wid = tid >> 5;
    const int ni2 = wid & 1, kspl = wid >> 1;
    const int cta = blockIdx.x, j0 = cta * 8;
    const unsigned smb = (unsigned)__cvta_generic_to_shared(sstg);

    // ---------- prologue: pack this CTA's weight slice into fragment images --
    {
        const float* Ws[4] = { Wih0, Whh0, Wih1, Whh1 };
        const int kd[4] = { D_, H_, H_, H_ };
        const int soff[4] = { 0, 32, 96, 160 };
#pragma unroll 1
        for (int ms = 0; ms < 4; ms++) {
            int Kdim = kd[ms], Kh = Kdim >> 1;
            const float* W = Ws[ms];
#pragma unroll 1
            for (int i = tid; i < 32 * Kh; i += NTHR) {
                int p = i % Kh, r = i / Kh;
                int grow = (r >> 3) * H_ + j0 + (r & 7);
                float2 v = *(const float2*)(W + (size_t)grow * Kdim + 2 * p);
                uint32_t hw, lw;
                bsplit(v.x, v.y, hw, lw);
                int slab = soff[ms] + (p >> 3);
                size_t base = ((size_t)cta * WSLAB + slab) * 2048 + (r >> 4) * 512 +
                              ((r & 7) * 4 + (p & 3)) * 16 +
                              (((p & 7) >> 2) * 2 + ((r >> 3) & 1)) * 4;
                *(uint32_t*)(g_wimg + base) = hw;
                *(uint32_t*)(g_wimg + base + 1024) = lw;
            }
        }
        // pack x slice: global pair indices [cta*131072, +131072)
        size_t i0 = (size_t)cta * 131072;
#pragma unroll 1
        for (int k = 0; k < 512; k++) {
            size_t i = i0 + (size_t)k * NTHR + tid;
            int p = (int)(i & 255);
            int t = (int)((i >> 8) & 1023);
            int b = (int)(i >> 18);
            float2 v = *(const float2*)(x + ((size_t)b * S_ + t) * D_ + 2 * p);
            uint32_t hw, lw;
            bsplit(v.x, v.y, hw, lw);
            size_t base = ((size_t)t * 32 + (p >> 3)) * 4096 + (b >> 3) * 256 +
                          ((b & 7) * 4 + (p & 3)) * 8 + ((p & 7) >> 2) * 4;
            *(uint32_t*)(g_ximg + base) = hw;
            *(uint32_t*)(g_ximg + base + 2048) = lw;
        }
        // zero initial h images (buffer 0)
        int idx = cta * NTHR + tid;
        if (idx < 16384) ((uint4*)g_h0img[0])[idx] = make_uint4(0, 0, 0, 0);
        else             ((uint4*)g_h1img[0])[idx - 16384] = make_uint4(0, 0, 0, 0);
    }
    if (tid < 64) {
        int L = tid >> 5, g = tid & 31;
        int grow = (g >> 3) * H_ + j0 + (g & 7);
        sbias[L][g] = L ? (bih1[grow] + bhh1[grow]) : (bih0[grow] + bhh0[grow]);
    }
    float cst0[2] = {0.f, 0.f}, cst1[2] = {0.f, 0.f};
    float* coutp = out + (size_t)B_ * S_ * H_;
    float* h1f = out + 2ull * B_ * S_ * H_;
    float* c1f = h1f + (size_t)B_ * H_;

    unsigned gen = *(volatile unsigned*)&g_bar_gen;
    grid_barrier(gen);   // prep complete grid-wide

    const u8* wcta = g_wimg + (size_t)cta * WSLAB * 2048;

    for (int t = 0; t < S_; t++) {
        const int rb = t & 1, wbuf = rb ^ 1;
        {
            float acc[2][4][4] = {};
            run_phase(g_ximg + (size_t)t * 131072, 32, g_h0img[rb], wcta, NSLAB0,
                      sstg, smb, tid, lane, ni2, kspl, acc);
            epi<0>(acc, sgate, sbias[0], tid, lane, ni2, kspl, j0, t, cst0,
                   g_h0img[wbuf], out, coutp, h1f, c1f);
        }
        grid_barrier(gen);
        {
            float acc[2][4][4] = {};
            run_phase(g_h0img[wbuf], 64, g_h1img[rb], wcta + (size_t)NSLAB0 * 2048,
                      NSLAB1, sstg, smb, tid, lane, ni2, kspl, acc);
            epi<1>(acc, sgate, sbias[1], tid, lane, ni2, kspl, j0, t, cst1,
                   g_h1img[wbuf], out, coutp, h1f, c1f);
        }
    }
}

extern "C" void kernel_launch(void* const* d_in, const int* in_sizes, int n_in,
                              void* d_out, int out_size) {
    cudaFuncSetAttribute(lstm_mma_kernel,
                         cudaFuncAttributeMaxDynamicSharedMemorySize, DYN_SMEM);
    lstm_mma_kernel<<<NCTA, NTHR, DYN_SMEM>>>(
        (const float*)d_in[0],
        (const float*)d_in[1], (const float*)d_in[2],
        (const float*)d_in[5], (const float*)d_in[6],
        (const float*)d_in[3], (const float*)d_in[4],
        (const float*)d_in[7], (const float*)d_in[8],
        (float*)d_out);
}